// round 4
// baseline (speedup 1.0000x reference)
#include <cuda_runtime.h>
#include <cstdint>

#define DD 1024
#define RR 4096
#define BB 32
#define NEG_INF_F (-1e9f)

// Scratch (no device allocation allowed in kernel_launch)
__device__ float g_projv[BB * DD];
__device__ float g_scores[BB * RR];

// ---------------------------------------------------------------------------
// helpers
// ---------------------------------------------------------------------------
__device__ __forceinline__ uint32_t f2tf(float x) {
    uint32_t r;
    asm("cvt.rna.tf32.f32 %0, %1;" : "=r"(r) : "f"(x));
    return r;
}

__device__ __forceinline__ float fast_tanh(float x) {
    // tanh(x) = 1 - 2/(e^{2x}+1); EX2+RCP based, ~2^-20 rel err.
    float e = __expf(2.0f * x);
    return 1.0f - __fdividef(2.0f, e + 1.0f);
}

__device__ __forceinline__ void mma_tf32(float c[4], const uint32_t a[4], const uint32_t b[2]) {
    asm volatile(
        "mma.sync.aligned.m16n8k8.row.col.f32.tf32.tf32.f32 "
        "{%0,%1,%2,%3}, {%4,%5,%6,%7}, {%8,%9}, {%0,%1,%2,%3};\n"
        : "+f"(c[0]), "+f"(c[1]), "+f"(c[2]), "+f"(c[3])
        : "r"(a[0]), "r"(a[1]), "r"(a[2]), "r"(a[3]), "r"(b[0]), "r"(b[1]));
}

__device__ __forceinline__ void cp_async16(uint32_t sdst, const void* gsrc) {
    asm volatile("cp.async.cg.shared.global [%0], [%1], 16;\n" :: "r"(sdst), "l"(gsrc));
}

// ---------------------------------------------------------------------------
// Kernel 1: proj_v = vector @ W   (B x D), fp32
// grid (D/256, B), 256 threads
// ---------------------------------------------------------------------------
__global__ void projv_kernel(const float* __restrict__ vec, const float* __restrict__ W) {
    __shared__ float vs[DD];
    const int b = blockIdx.y;
    const int n = blockIdx.x * 256 + threadIdx.x;
    for (int k = threadIdx.x; k < DD; k += 256) vs[k] = vec[b * DD + k];
    __syncthreads();
    float acc = 0.0f;
#pragma unroll 8
    for (int k = 0; k < DD; ++k) acc = fmaf(vs[k], W[(size_t)k * DD + n], acc);
    g_projv[b * DD + n] = acc;
}

// ---------------------------------------------------------------------------
// Kernel 2: fused proj_m GEMM (tf32 mma.sync) + tanh(+proj_v) . v -> scores
// CTA tile: 128 rows x 128 cols per N-pass, 8 N-passes cover D=1024.
// grid (R/128, B), 256 threads, dynamic smem 72192B, double-buffered cp.async.
// ---------------------------------------------------------------------------
// smem layout (floats): As[2][128][36] @0 (9216), Bs[2][32][136] @9216 (8704),
//                        s_score[128] @17920. Total 18048 floats = 72192 B.
#define AS_STRIDE 36
#define BS_STRIDE 136
#define AS_BUF    4608
#define BS_BUF    4352

__global__ __launch_bounds__(256, 2)
void fused_gemm_kernel(const float* __restrict__ matrix,
                       const float* __restrict__ Umat,
                       const float* __restrict__ vvec) {
    extern __shared__ float smem[];
    float* As = smem;
    float* Bs = smem + 2 * AS_BUF;
    float* s_score = smem + 2 * AS_BUF + 2 * BS_BUF;

    const int tid = threadIdx.x;
    const int b = blockIdx.y;
    const int row0 = blockIdx.x * 128;

    const int warp = tid >> 5;
    const int lane = tid & 31;
    const int wm = warp & 3;   // warp M index (0..3), 32 rows each
    const int wn = warp >> 2;  // warp N index (0..1), 64 cols each
    const int g = lane >> 2;   // groupID
    const int t = lane & 3;    // thread-in-group

    if (tid < 128) s_score[tid] = 0.0f;

    const float* Ag = matrix + ((size_t)b * RR + row0) * DD;
    const uint32_t As_base = (uint32_t)__cvta_generic_to_shared(As);
    const uint32_t Bs_base = (uint32_t)__cvta_generic_to_shared(Bs);

    // copy indices (each thread moves 4 float4 per tile per operand)
    const int am = tid >> 3, ac = (tid & 7) * 4;          // A: +32 rows per step
    const int bk = tid >> 5, bc = (tid & 31) * 4;         // B: +8 rows per step

    for (int nt = 0; nt < 8; ++nt) {
        const int n0 = nt * 128;

        float acc[2][8][4];
#pragma unroll
        for (int i = 0; i < 2; ++i)
#pragma unroll
            for (int j = 0; j < 8; ++j)
#pragma unroll
                for (int q = 0; q < 4; ++q) acc[i][j][q] = 0.0f;

        // prefetch kt=0 into buffer 0
        {
#pragma unroll
            for (int i = 0; i < 4; ++i) {
                const int m = am + i * 32;
                cp_async16(As_base + (uint32_t)(m * AS_STRIDE + ac) * 4u, Ag + (size_t)m * DD + ac);
            }
#pragma unroll
            for (int i = 0; i < 4; ++i) {
                const int k = bk + i * 8;
                cp_async16(Bs_base + (uint32_t)(k * BS_STRIDE + bc) * 4u, Umat + (size_t)k * DD + n0 + bc);
            }
            asm volatile("cp.async.commit_group;\n");
        }

        for (int kt = 0; kt < 32; ++kt) {
            const int cur = kt & 1;
            if (kt < 31) {
                const int k0 = (kt + 1) * 32;
                const int nb = cur ^ 1;
#pragma unroll
                for (int i = 0; i < 4; ++i) {
                    const int m = am + i * 32;
                    cp_async16(As_base + (uint32_t)(nb * AS_BUF + m * AS_STRIDE + ac) * 4u,
                               Ag + (size_t)m * DD + k0 + ac);
                }
#pragma unroll
                for (int i = 0; i < 4; ++i) {
                    const int k = bk + i * 8;
                    cp_async16(Bs_base + (uint32_t)(nb * BS_BUF + k * BS_STRIDE + bc) * 4u,
                               Umat + (size_t)(k0 + k) * DD + n0 + bc);
                }
                asm volatile("cp.async.commit_group;\n");
                asm volatile("cp.async.wait_group 1;\n");
            } else {
                asm volatile("cp.async.wait_group 0;\n");
            }
            __syncthreads();

            const float* Ab = As + cur * AS_BUF;
            const float* Bb = Bs + cur * BS_BUF;
#pragma unroll
            for (int ks = 0; ks < 4; ++ks) {
                const int kk = ks * 8;
                uint32_t afr[2][4];
#pragma unroll
                for (int i = 0; i < 2; ++i) {
                    const int r = wm * 32 + i * 16 + g;
                    afr[i][0] = f2tf(Ab[r * AS_STRIDE + kk + t]);
                    afr[i][1] = f2tf(Ab[(r + 8) * AS_STRIDE + kk + t]);
                    afr[i][2] = f2tf(Ab[r * AS_STRIDE + kk + t + 4]);
                    afr[i][3] = f2tf(Ab[(r + 8) * AS_STRIDE + kk + t + 4]);
                }
                uint32_t bfr[8][2];
#pragma unroll
                for (int j = 0; j < 8; ++j) {
                    const int cc = wn * 64 + j * 8 + g;
                    bfr[j][0] = f2tf(Bb[(kk + t) * BS_STRIDE + cc]);
                    bfr[j][1] = f2tf(Bb[(kk + t + 4) * BS_STRIDE + cc]);
                }
#pragma unroll
                for (int i = 0; i < 2; ++i)
#pragma unroll
                    for (int j = 0; j < 8; ++j)
                        mma_tf32(acc[i][j], afr[i], bfr[j]);
            }
            __syncthreads();
        }

        // Epilogue: tanh(acc + proj_v) * v, reduce over N into per-row partials
        const float* pv = g_projv + b * DD;
        float ps[2][2] = {{0.0f, 0.0f}, {0.0f, 0.0f}};
#pragma unroll
        for (int j = 0; j < 8; ++j) {
            const int cb = n0 + wn * 64 + j * 8 + 2 * t;
            const float2 pvv = *(const float2*)(pv + cb);
            const float2 vv = *(const float2*)(vvec + cb);
#pragma unroll
            for (int i = 0; i < 2; ++i) {
                ps[i][0] += fast_tanh(acc[i][j][0] + pvv.x) * vv.x
                          + fast_tanh(acc[i][j][1] + pvv.y) * vv.y;
                ps[i][1] += fast_tanh(acc[i][j][2] + pvv.x) * vv.x
                          + fast_tanh(acc[i][j][3] + pvv.y) * vv.y;
            }
        }
        // reduce across the 4 lanes of each group (t dimension)
#pragma unroll
        for (int i = 0; i < 2; ++i)
#pragma unroll
            for (int h = 0; h < 2; ++h) {
                float x = ps[i][h];
                x += __shfl_xor_sync(0xffffffffu, x, 1);
                x += __shfl_xor_sync(0xffffffffu, x, 2);
                if (t == 0) atomicAdd(&s_score[wm * 32 + i * 16 + h * 8 + g], x);
            }
    }

    __syncthreads();
    if (tid < 128) g_scores[(size_t)b * RR + row0 + tid] = s_score[tid];
}

// ---------------------------------------------------------------------------
// Kernel 3: masked softmax over R per batch
// grid (B), 256 threads, 16 elems each
// ---------------------------------------------------------------------------
__global__ void softmax_kernel(const int* __restrict__ mask, float* __restrict__ out) {
    const int b = blockIdx.x;
    __shared__ float red[256];
    const float* s = g_scores + (size_t)b * RR;
    const int* m = mask + (size_t)b * RR;

    float l[16];
    float lmax = -3.0e38f;
#pragma unroll
    for (int i = 0; i < 16; ++i) {
        const int r = threadIdx.x + i * 256;
        l[i] = (m[r] > 0) ? s[r] : NEG_INF_F;
        lmax = fmaxf(lmax, l[i]);
    }
    red[threadIdx.x] = lmax;
    __syncthreads();
    for (int off = 128; off > 0; off >>= 1) {
        if (threadIdx.x < off) red[threadIdx.x] = fmaxf(red[threadIdx.x], red[threadIdx.x + off]);
        __syncthreads();
    }
    const float gmax = red[0];
    __syncthreads();

    float e[16];
    float lsum = 0.0f;
#pragma unroll
    for (int i = 0; i < 16; ++i) {
        e[i] = __expf(l[i] - gmax);
        lsum += e[i];
    }
    red[threadIdx.x] = lsum;
    __syncthreads();
    for (int off = 128; off > 0; off >>= 1) {
        if (threadIdx.x < off) red[threadIdx.x] += red[threadIdx.x + off];
        __syncthreads();
    }
    const float inv = __frcp_rn(red[0]);
#pragma unroll
    for (int i = 0; i < 16; ++i)
        out[(size_t)b * RR + threadIdx.x + i * 256] = e[i] * inv;
}

// ---------------------------------------------------------------------------
// launch
// ---------------------------------------------------------------------------
extern "C" void kernel_launch(void* const* d_in, const int* in_sizes, int n_in,
                              void* d_out, int out_size) {
    (void)in_sizes; (void)n_in; (void)out_size;
    const float* vec    = (const float*)d_in[0];  // (32,1024)
    const float* matrix = (const float*)d_in[1];  // (32,4096,1024)
    const int*   mask   = (const int*)  d_in[2];  // (32,4096)
    const float* W      = (const float*)d_in[3];  // (1024,1024)
    const float* U      = (const float*)d_in[4];  // (1024,1024)
    const float* v      = (const float*)d_in[5];  // (1024,1)
    float* out = (float*)d_out;                   // (32,4096)

    const int SMEM = (2 * AS_BUF + 2 * BS_BUF + 128) * 4;  // 72192 B
    cudaFuncSetAttribute(fused_gemm_kernel, cudaFuncAttributeMaxDynamicSharedMemorySize, SMEM);

    projv_kernel<<<dim3(DD / 256, BB), 256>>>(vec, W);
    fused_gemm_kernel<<<dim3(RR / 128, BB), 256, SMEM>>>(matrix, U, v);
    softmax_kernel<<<BB, 256>>>(mask, out);
}

// round 6
// speedup vs baseline: 1.6848x; 1.6848x over previous
#include <cuda_runtime.h>
#include <cstdint>

#define DD 1024
#define RR 4096
#define BB 32
#define NEG_INF_F (-1e9f)

// Scratch (no device allocation allowed anywhere)
__device__ float g_projv[BB * DD];
__device__ float g_scores[BB * RR];
__device__ float g_Ur[DD * DD];   // U pre-rounded to tf32 bit patterns (same layout)

// ---------------------------------------------------------------------------
// helpers
// ---------------------------------------------------------------------------
__device__ __forceinline__ uint32_t f2tf(float x) {
    uint32_t r;
    asm("cvt.rna.tf32.f32 %0, %1;" : "=r"(r) : "f"(x));
    return r;
}

__device__ __forceinline__ float fast_tanh(float x) {
    float e = __expf(2.0f * x);
    return 1.0f - __fdividef(2.0f, e + 1.0f);
}

__device__ __forceinline__ void mma_tf32(float c[4], const uint32_t a[4], const uint32_t b[2]) {
    asm volatile(
        "mma.sync.aligned.m16n8k8.row.col.f32.tf32.tf32.f32 "
        "{%0,%1,%2,%3}, {%4,%5,%6,%7}, {%8,%9}, {%0,%1,%2,%3};\n"
        : "+f"(c[0]), "+f"(c[1]), "+f"(c[2]), "+f"(c[3])
        : "r"(a[0]), "r"(a[1]), "r"(a[2]), "r"(a[3]), "r"(b[0]), "r"(b[1]));
}

__device__ __forceinline__ void cp_async16(uint32_t sdst, const void* gsrc) {
    asm volatile("cp.async.cg.shared.global [%0], [%1], 16;\n" :: "r"(sdst), "l"(gsrc));
}

// ---------------------------------------------------------------------------
// Kernel 0: pre-round U to tf32 bit patterns (removes runtime cvt on B side)
// ---------------------------------------------------------------------------
__global__ void roundU_kernel(const float* __restrict__ U) {
    const int idx = (blockIdx.x * 256 + threadIdx.x) * 4;
    float4 u = *(const float4*)(U + idx);
    u.x = __uint_as_float(f2tf(u.x));
    u.y = __uint_as_float(f2tf(u.y));
    u.z = __uint_as_float(f2tf(u.z));
    u.w = __uint_as_float(f2tf(u.w));
    *(float4*)(g_Ur + idx) = u;
}

// ---------------------------------------------------------------------------
// Kernel 1: proj_v = vector @ W  (B x D) fp32, k-split x4 within block
// ---------------------------------------------------------------------------
__global__ void projv_kernel(const float* __restrict__ vec, const float* __restrict__ W) {
    __shared__ float vs[DD];
    __shared__ float part[4][64];
    const int b = blockIdx.y;
    const int n0 = blockIdx.x * 64;
    const int n = threadIdx.x & 63;
    const int kp = threadIdx.x >> 6;

    for (int k = threadIdx.x; k < DD; k += 256) vs[k] = vec[b * DD + k];
    __syncthreads();

    const float* Wp = W + (size_t)(kp * 256) * DD + n0 + n;
    const float* vp = vs + kp * 256;
    float acc = 0.0f;
#pragma unroll 8
    for (int k = 0; k < 256; ++k) acc = fmaf(vp[k], Wp[(size_t)k * DD], acc);
    part[kp][n] = acc;
    __syncthreads();
    if (kp == 0)
        g_projv[b * DD + n0 + n] = part[0][n] + part[1][n] + part[2][n] + part[3][n];
}

// ---------------------------------------------------------------------------
// Kernel 2: fused proj_m GEMM (legacy tf32 mma.sync, warp tile 64x64)
//           + tanh(+proj_v).v row reduction
// CTA tile 128(M) x 256(N), K-chunk 32, 3 smem slots, cp.async 2-deep.
// grid (R/128, B) = (32, 32), 256 threads (8 warps, 2Mx4N).
// smem stage (floats): A 128x32 (XOR-swizzled, 4096) + B 32x264 (8448) = 12544.
// 3 stages + 128 score floats = 37760 floats = 151040 B.
// ---------------------------------------------------------------------------
#define STG_F  12544
#define B_OFF  4096
#define BSTR   264
#define NTOT   128           // 4 N-passes x 32 k-chunks

__global__ __launch_bounds__(256, 1)
void fused_gemm_legacy(const float* __restrict__ matrix, const float* __restrict__ vvec) {
    extern __shared__ __align__(128) float smem[];
    float* s_score = smem + 3 * STG_F;

    const int tid = threadIdx.x;
    const int warp = tid >> 5;
    const int lane = tid & 31;
    const int wm = warp & 1;       // 0..1  (64 rows each)
    const int wn = warp >> 1;      // 0..3  (64 cols each)
    const int g = lane >> 2;       // 0..7
    const int t = lane & 3;        // 0..3

    const int b = blockIdx.y;
    const int row0 = blockIdx.x * 128;

    if (tid < 128) s_score[tid] = 0.0f;

    const float* Ag = matrix + ((size_t)b * RR + row0) * DD;
    const uint32_t sb = (uint32_t)__cvta_generic_to_shared(smem);

    // cp.async thread mappings
    const int ar = tid >> 3, ac = tid & 7;     // A: (row base, 16B chunk)
    const int br = tid >> 6, bc = tid & 63;    // B: (k-row base, 16B chunk)
    const uint32_t a_sw = (uint32_t)(ar & 7);  // row&7 invariant under +32

    auto issue_loads = [&](int sl) {
        const uint32_t slot = (uint32_t)(sl % 3);
        const int kt = sl & 31;
        const int n0 = (sl >> 5) * 256;
        const uint32_t abase = sb + slot * (STG_F * 4u);
        const uint32_t bbase = abase + B_OFF * 4u;
        const float* asrc = Ag + (size_t)ar * DD + kt * 32 + ac * 4;
#pragma unroll
        for (int i = 0; i < 4; ++i) {
            const int row = ar + i * 32;
            cp_async16(abase + (uint32_t)(row * 128) + ((((uint32_t)ac) ^ a_sw) << 4),
                       asrc + (size_t)i * 32 * DD);
        }
        const float* bsrc = g_Ur + (size_t)(kt * 32 + br) * DD + n0 + bc * 4;
#pragma unroll
        for (int i = 0; i < 8; ++i)
            cp_async16(bbase + (uint32_t)((br + i * 4) * (BSTR * 4)) + ((uint32_t)bc << 4),
                       bsrc + (size_t)i * 4 * DD);
    };

    // prefetch slots 0,1
    issue_loads(0);
    asm volatile("cp.async.commit_group;\n");
    issue_loads(1);
    asm volatile("cp.async.commit_group;\n");

    float acc[4][8][4];
#pragma unroll
    for (int i = 0; i < 4; ++i)
#pragma unroll
        for (int j = 0; j < 8; ++j)
#pragma unroll
            for (int q = 0; q < 4; ++q) acc[i][j][q] = 0.0f;

    const float* pv = g_projv + b * DD;

    for (int s = 0; s < NTOT; ++s) {
        const int sl = s + 2;
        if (sl < NTOT) issue_loads(sl);
        asm volatile("cp.async.commit_group;\n");
        asm volatile("cp.async.wait_group 2;\n");
        __syncthreads();

        const float* Ab = smem + (s % 3) * STG_F;
        const float* Bb = Ab + B_OFF;

#pragma unroll
        for (int ks = 0; ks < 4; ++ks) {
            // A fragments: A[row][col], addr = row*32 + ((col>>2)^g)*4 + (col&3)
            const int cxa = ((2 * ks) ^ g) * 4 + t;
            const int cxb = ((2 * ks + 1) ^ g) * 4 + t;
            uint32_t afr[4][4];
#pragma unroll
            for (int i = 0; i < 4; ++i) {
                const int r0 = (wm * 64 + i * 16 + g) * 32;
                afr[i][0] = f2tf(Ab[r0 + cxa]);
                afr[i][1] = f2tf(Ab[r0 + 256 + cxa]);   // +8 rows
                afr[i][2] = f2tf(Ab[r0 + cxb]);
                afr[i][3] = f2tf(Ab[r0 + 256 + cxb]);
            }
            uint32_t bfr[8][2];
            const int kb = (ks * 8 + t) * BSTR;
#pragma unroll
            for (int j = 0; j < 8; ++j) {
                const int cc = wn * 64 + j * 8 + g;
                bfr[j][0] = __float_as_uint(Bb[kb + cc]);
                bfr[j][1] = __float_as_uint(Bb[kb + 4 * BSTR + cc]);
            }
#pragma unroll
            for (int i = 0; i < 4; ++i)
#pragma unroll
                for (int j = 0; j < 8; ++j)
                    mma_tf32(acc[i][j], afr[i], bfr[j]);
        }

        if ((s & 31) == 31) {
            // epilogue for this 256-col pass: tanh(acc + pv) . v
            const int n0 = (s >> 5) * 256;
            float ps[4][2];
#pragma unroll
            for (int i = 0; i < 4; ++i) { ps[i][0] = 0.0f; ps[i][1] = 0.0f; }
#pragma unroll
            for (int j = 0; j < 8; ++j) {
                const int cb = n0 + wn * 64 + j * 8 + 2 * t;
                const float2 pvv = *(const float2*)(pv + cb);
                const float2 vv = *(const float2*)(vvec + cb);
#pragma unroll
                for (int i = 0; i < 4; ++i) {
                    ps[i][0] += fast_tanh(acc[i][j][0] + pvv.x) * vv.x
                              + fast_tanh(acc[i][j][1] + pvv.y) * vv.y;
                    ps[i][1] += fast_tanh(acc[i][j][2] + pvv.x) * vv.x
                              + fast_tanh(acc[i][j][3] + pvv.y) * vv.y;
                    acc[i][j][0] = 0.0f; acc[i][j][1] = 0.0f;
                    acc[i][j][2] = 0.0f; acc[i][j][3] = 0.0f;
                }
            }
#pragma unroll
            for (int i = 0; i < 4; ++i)
#pragma unroll
                for (int h = 0; h < 2; ++h) {
                    float x = ps[i][h];
                    x += __shfl_xor_sync(0xffffffffu, x, 1);
                    x += __shfl_xor_sync(0xffffffffu, x, 2);
                    if (t == 0) atomicAdd(&s_score[wm * 64 + i * 16 + h * 8 + g], x);
                }
        }
        __syncthreads();   // protects smem slot reuse by next issue_loads
    }

    if (tid < 128) g_scores[(size_t)b * RR + row0 + tid] = s_score[tid];
}

// ---------------------------------------------------------------------------
// Kernel 3: masked softmax over R per batch. grid (B), 256 threads.
// ---------------------------------------------------------------------------
__global__ void softmax_kernel(const int* __restrict__ mask, float* __restrict__ out) {
    const int b = blockIdx.x;
    __shared__ float red[256];
    const float* s = g_scores + (size_t)b * RR;
    const int* m = mask + (size_t)b * RR;

    float l[16];
    float lmax = -3.0e38f;
#pragma unroll
    for (int i = 0; i < 16; ++i) {
        const int r = threadIdx.x + i * 256;
        l[i] = (m[r] > 0) ? s[r] : NEG_INF_F;
        lmax = fmaxf(lmax, l[i]);
    }
    red[threadIdx.x] = lmax;
    __syncthreads();
    for (int off = 128; off > 0; off >>= 1) {
        if (threadIdx.x < off) red[threadIdx.x] = fmaxf(red[threadIdx.x], red[threadIdx.x + off]);
        __syncthreads();
    }
    const float gmax = red[0];
    __syncthreads();

    float e[16];
    float lsum = 0.0f;
#pragma unroll
    for (int i = 0; i < 16; ++i) {
        e[i] = __expf(l[i] - gmax);
        lsum += e[i];
    }
    red[threadIdx.x] = lsum;
    __syncthreads();
    for (int off = 128; off > 0; off >>= 1) {
        if (threadIdx.x < off) red[threadIdx.x] += red[threadIdx.x + off];
        __syncthreads();
    }
    const float inv = __frcp_rn(red[0]);
#pragma unroll
    for (int i = 0; i < 16; ++i)
        out[(size_t)b * RR + threadIdx.x + i * 256] = e[i] * inv;
}

// ---------------------------------------------------------------------------
// launch
// ---------------------------------------------------------------------------
extern "C" void kernel_launch(void* const* d_in, const int* in_sizes, int n_in,
                              void* d_out, int out_size) {
    (void)in_sizes; (void)n_in; (void)out_size;
    const float* vec    = (const float*)d_in[0];  // (32,1024)
    const float* matrix = (const float*)d_in[1];  // (32,4096,1024)
    const int*   mask   = (const int*)  d_in[2];  // (32,4096)
    const float* W      = (const float*)d_in[3];  // (1024,1024)
    const float* U      = (const float*)d_in[4];  // (1024,1024)
    const float* v      = (const float*)d_in[5];  // (1024,1)
    float* out = (float*)d_out;                   // (32,4096)

    const int SMEM = (3 * STG_F + 128) * 4;  // 151040 B
    static int configured = 0;
    if (!configured) {
        cudaFuncSetAttribute(fused_gemm_legacy, cudaFuncAttributeMaxDynamicSharedMemorySize, SMEM);
        configured = 1;
    }

    roundU_kernel<<<DD * DD / 1024, 256>>>(U);
    projv_kernel<<<dim3(DD / 64, BB), 256>>>(vec, W);
    fused_gemm_legacy<<<dim3(RR / 128, BB), 256, SMEM>>>(matrix, v);
    softmax_kernel<<<BB, 256>>>(mask, out);
}